// round 16
// baseline (speedup 1.0000x reference)
#include <cuda_runtime.h>
#include <cuda_fp16.h>
#include <cstdint>

// ===================== device scratch (no allocs allowed) =====================
__device__ __half g_t12h[64 * 64 * 64];         // [m=(o12,i12)][r]   (A of W-GEMM)
__device__ __half g_t34h[64 * 64 * 64];         // [n=(o34,i34)][r]   (B of W-GEMM)
__device__ __half g_W[4096ull * 4096ull];       // [n][k] fp16 (main GEMM B)
__device__ __half g_X[16384ull * 4096ull];      // [m][k] fp16 (main GEMM A)
__device__ unsigned g_convdone[128];            // per-128-row-group conv counters (monotone)

// ===================== helpers =====================
__device__ __forceinline__ uint32_t smem_u32(const void* p) {
    uint32_t a;
    asm("{ .reg .u64 t; cvta.to.shared.u64 t, %1; cvt.u32.u64 %0, t; }" : "=r"(a) : "l"(p));
    return a;
}
__device__ __forceinline__ void cp16(uint32_t s, const void* g) {
    asm volatile("cp.async.cg.shared.global [%0], [%1], 16;" :: "r"(s), "l"(g));
}
#define CP_COMMIT() asm volatile("cp.async.commit_group;" ::: "memory")
#define CP_WAIT(n)  asm volatile("cp.async.wait_group %0;" :: "n"(n) : "memory")

__device__ __forceinline__ void ldsm_x4(uint32_t& r0, uint32_t& r1, uint32_t& r2, uint32_t& r3,
                                        uint32_t addr) {
    asm volatile("ldmatrix.sync.aligned.m8n8.x4.shared.b16 {%0,%1,%2,%3}, [%4];"
                 : "=r"(r0), "=r"(r1), "=r"(r2), "=r"(r3) : "r"(addr));
}
__device__ __forceinline__ void mma16816(float* d, const uint32_t* a, const uint32_t* b) {
    asm volatile("mma.sync.aligned.m16n8k16.row.col.f32.f16.f16.f32 "
                 "{%0,%1,%2,%3}, {%4,%5,%6,%7}, {%8,%9}, {%0,%1,%2,%3};"
                 : "+f"(d[0]), "+f"(d[1]), "+f"(d[2]), "+f"(d[3])
                 : "r"(a[0]), "r"(a[1]), "r"(a[2]), "r"(a[3]), "r"(b[0]), "r"(b[1]));
}

// ===================== problem constants =====================
static constexpr int M_TOTAL = 16384, N_TOTAL = 4096, K_TOTAL = 4096;
static constexpr int BM = 128, BN = 128, BK = 64, STAGES = 3;
static constexpr int KITERS = K_TOTAL / BK;                  // 64
static constexpr uint32_t ROW_B = 144;                       // 128B data + 16B pad
static constexpr uint32_t STAGE_ROWS = BM + BN;              // 256 (A: 0..127, B: 128..255)
static constexpr uint32_t STAGE_BYTES = STAGE_ROWS * ROW_B;  // 36864
static constexpr uint32_t SMEM_TOTAL = STAGES * STAGE_BYTES; // 110592 -> 2 CTAs/SM

// ===================== kernel 0: t12h / t34h (fp16 TT pair contractions) =================
__global__ __launch_bounds__(256) void k_prep(const float* __restrict__ c0,
                                              const float* __restrict__ c1,
                                              const float* __restrict__ c2,
                                              const float* __restrict__ c3) {
    int bid = blockIdx.x;
    if (bid < 1024) {
        int idx = bid * 256 + threadIdx.x;            // (o12, i12, r3)
        int r3 = idx & 63, i12 = (idx >> 6) & 63, o12 = idx >> 12;
        int i1 = i12 >> 3, i2 = i12 & 7, o1 = o12 >> 3, o2 = o12 & 7;
        const float* g1 = c0 + (i1 * 8 + o1) * 64;              // [r2]
        const float* g2 = c1 + (i2 * 8 + o2) * 64 + r3;         // + r2*4096
        float acc = 0.f;
        #pragma unroll 8
        for (int r2 = 0; r2 < 64; ++r2) acc += g1[r2] * g2[r2 * 4096];
        g_t12h[(o12 * 64 + i12) * 64 + r3] = __float2half_rn(acc);   // A[m][r]
    } else {
        int idx = (bid - 1024) * 256 + threadIdx.x;   // (r3, o34, i34)
        int i34 = idx & 63, o34 = (idx >> 6) & 63, r3 = idx >> 12;
        int i3 = i34 >> 3, i4 = i34 & 7, o3 = o34 >> 3, o4 = o34 & 7;
        const float* g3 = c2 + ((r3 * 8 + i3) * 8 + o3) * 64;   // [r4]
        const float* g4 = c3 + (i4 * 8 + o4);                   // + r4*64
        float acc = 0.f;
        #pragma unroll 8
        for (int r4 = 0; r4 < 64; ++r4) acc += g3[r4] * g4[r4 * 64];
        g_t34h[(o34 * 64 + i34) * 64 + r3] = __float2half_rn(acc);   // B[n][r] (transposed)
    }
}

// ===================== kernel 1a: W via HMMA (M=4096, N=4096, K=64) + MPO scatter ========
// W[(o12,o34)][(i12,i34)] = sum_r t12[(o12,i12)][r] * t34[(o34,i34)][r]
__global__ void __launch_bounds__(128, 2) k_buildW_mma(void) {
    extern __shared__ char smem[];
    const uint32_t sbase = smem_u32(smem);
    const int tid = threadIdx.x, wid = tid >> 5, lid = tid & 31;

    const int m0 = (blockIdx.x >> 5) * BM;    // m = (o12, i12)
    const int n0 = (blockIdx.x & 31) * BN;    // n = (o34, i34)

    const int warp_m = wid >> 1;
    const int warp_n = wid & 1;

    const uint32_t a_lane_off =
        (uint32_t)(warp_m * 64 + (lid & 7) + ((lid >> 3) & 1) * 8) * ROW_B +
        (uint32_t)((lid >> 4) & 1) * 16u;
    const uint32_t b_lane_off =
        (uint32_t)(BM + warp_n * 64 + (((lid >> 3) >> 1) & 1) * 8 + (lid & 7)) * ROW_B +
        (uint32_t)((lid >> 3) & 1) * 16u;

    // Single stage: K_TOTAL == BK == 64 (64 halves = 128B per row = 8 x 16B chunks).
    #pragma unroll
    for (int it = 0; it < 16; ++it) {
        const int idx = it * 128 + tid;          // 0..2047
        const int row = idx >> 3, c = idx & 7;
        const uint32_t sa = sbase + (uint32_t)row * ROW_B + (uint32_t)c * 16u;
        const __half* g = (row < BM)
            ? (g_t12h + (size_t)(m0 + row) * 64 + c * 8)
            : (g_t34h + (size_t)(n0 + row - BM) * 64 + c * 8);
        cp16(sa, g);
    }
    CP_COMMIT();
    CP_WAIT(0);
    __syncthreads();

    float acc[4][8][4];
    #pragma unroll
    for (int mt = 0; mt < 4; ++mt)
        #pragma unroll
        for (int nt = 0; nt < 8; ++nt)
            #pragma unroll
            for (int j = 0; j < 4; ++j) acc[mt][nt][j] = 0.f;

    #pragma unroll
    for (int ks = 0; ks < 4; ++ks) {
        const uint32_t koff = (uint32_t)ks * 32u;
        uint32_t afr[4][4], bfr[4][4];
        #pragma unroll
        for (int mt = 0; mt < 4; ++mt)
            ldsm_x4(afr[mt][0], afr[mt][1], afr[mt][2], afr[mt][3],
                    sbase + a_lane_off + (uint32_t)mt * (16u * ROW_B) + koff);
        #pragma unroll
        for (int p = 0; p < 4; ++p)
            ldsm_x4(bfr[p][0], bfr[p][1], bfr[p][2], bfr[p][3],
                    sbase + b_lane_off + (uint32_t)p * (16u * ROW_B) + koff);
        #pragma unroll
        for (int mt = 0; mt < 4; ++mt)
            #pragma unroll
            for (int p = 0; p < 4; ++p) {
                mma16816(acc[mt][2 * p],     afr[mt], &bfr[p][0]);
                mma16816(acc[mt][2 * p + 1], afr[mt], &bfr[p][2]);
            }
    }

    // Scatter epilogue: (m=(o12,i12), n=(o34,i34)) -> g_W[(o12*64+o34)][(i12*64+i34)]
    const int mbase = m0 + warp_m * 64 + (lid >> 2);
    const int nbase = n0 + warp_n * 64 + (lid & 3) * 2;
    #pragma unroll
    for (int mt = 0; mt < 4; ++mt) {
        #pragma unroll
        for (int half = 0; half < 2; ++half) {          // rows m, m+8 of the fragment
            const int m = mbase + mt * 16 + half * 8;
            const int o12 = m >> 6, i12 = m & 63;
            #pragma unroll
            for (int nt = 0; nt < 8; ++nt) {
                const int n = nbase + nt * 8;           // i34 stays within its 64-block
                const int o34 = n >> 6, i34 = n & 63;
                const size_t addr = (size_t)(o12 * 64 + o34) * 4096 + i12 * 64 + i34;
                __half2 v = __floats2half2_rn(acc[mt][nt][2 * half],
                                              acc[mt][nt][2 * half + 1]);
                *reinterpret_cast<__half2*>(&g_W[addr]) = v;
            }
        }
    }
}

// ===================== kernel 1b: convert x -> fp16 (one M row per block) ================
__global__ __launch_bounds__(256) void k_conv(const float* __restrict__ x) {
    // Block bid converts exactly row bid (4096 floats = 1024 float4).
    const size_t base = (size_t)blockIdx.x * 1024 + threadIdx.x;
    const float4* __restrict__ xi = reinterpret_cast<const float4*>(x);
    __half2* __restrict__ xo = reinterpret_cast<__half2*>(g_X);
    float4 v[4];
    #pragma unroll
    for (int j = 0; j < 4; ++j) v[j] = xi[base + j * 256];      // 4 independent loads in flight
    #pragma unroll
    for (int j = 0; j < 4; ++j) {
        const size_t t = base + j * 256;
        xo[2 * t]     = __floats2half2_rn(v[j].x, v[j].y);
        xo[2 * t + 1] = __floats2half2_rn(v[j].z, v[j].w);
    }
    // Publish readiness of this row (fence -> sync -> single atomic).
    __threadfence();
    __syncthreads();
    if (threadIdx.x == 0)
        atomicAdd(&g_convdone[blockIdx.x >> 7], 1u);
}

// ===================== kernel 2: GEMM 128x128x64, 4 warps of 64x64, 2 CTAs/SM ============
// FROZEN mainloop (R9/R10): interleaved cp.async + frag pipelining, tensor pipe 83%.
// Per-M-group spin gate replaces the conv->gemm graph edge.
__global__ void __launch_bounds__(128, 2) k_gemm(const float* __restrict__ bias,
                                                 float* __restrict__ out) {
    extern __shared__ char smem[];
    const uint32_t sbase = smem_u32(smem);
    const int tid = threadIdx.x, wid = tid >> 5, lid = tid & 31;

    const int m0 = (blockIdx.x >> 5) * BM;
    const int n0 = (blockIdx.x & 31) * BN;

    // Gate: wait until conv finished all 128 rows of this M group.
    // Counters are monotone across graph replays; X rewrites are value-identical,
    // so a warm gate passing early is still correct.
    if (tid == 0) {
        volatile unsigned* f = &g_convdone[m0 >> 7];
        while (*f < 128u) { __nanosleep(64); }
    }
    __syncthreads();
    __threadfence();   // acquire: conv's X stores visible before our loads

    const int warp_m = wid >> 1;
    const int warp_n = wid & 1;

    const uint32_t a_lane_off =
        (uint32_t)(warp_m * 64 + (lid & 7) + ((lid >> 3) & 1) * 8) * ROW_B +
        (uint32_t)((lid >> 4) & 1) * 16u;
    const uint32_t b_lane_off =
        (uint32_t)(BM + warp_n * 64 + (((lid >> 3) >> 1) & 1) * 8 + (lid & 7)) * ROW_B +
        (uint32_t)((lid >> 3) & 1) * 16u;

    const __half* __restrict__ Ag = g_X + (size_t)m0 * K_TOTAL;
    const __half* __restrict__ Bg = g_W + (size_t)n0 * K_TOTAL;

    auto load_quarter = [&](int st, int q) {
        const uint32_t sbuf = sbase + (uint32_t)(st % STAGES) * STAGE_BYTES;
        const int kk = st * BK;
        #pragma unroll
        for (int it = 0; it < 4; ++it) {
            const int idx = (q * 4 + it) * 128 + tid;
            const int row = idx >> 3, c = idx & 7;
            const uint32_t sa = sbuf + (uint32_t)row * ROW_B + (uint32_t)c * 16u;
            const __half* g = (row < BM)
                ? (Ag + (size_t)row * K_TOTAL + kk + c * 8)
                : (Bg + (size_t)(row - BM) * K_TOTAL + kk + c * 8);
            cp16(sa, g);
        }
    };
    auto load_stage = [&](int st) {
        #pragma unroll
        for (int q = 0; q < 4; ++q) load_quarter(st, q);
    };

    auto ld_frags = [&](uint32_t sbuf, int ks, uint32_t afr[4][4], uint32_t bfr[4][4]) {
        const uint32_t koff = (uint32_t)ks * 32u;
        #pragma unroll
        for (int mt = 0; mt < 4; ++mt)
            ldsm_x4(afr[mt][0], afr[mt][1], afr[mt][2], afr[mt][3],
                    sbuf + a_lane_off + (uint32_t)mt * (16u * ROW_B) + koff);
        #pragma unroll
        for (int p = 0; p < 4; ++p)
            ldsm_x4(bfr[p][0], bfr[p][1], bfr[p][2], bfr[p][3],
                    sbuf + b_lane_off + (uint32_t)p * (16u * ROW_B) + koff);
    };

    float acc[4][8][4];
    #pragma unroll
    for (int mt = 0; mt < 4; ++mt)
        #pragma unroll
        for (int nt = 0; nt < 8; ++nt)
            #pragma unroll
            for (int j = 0; j < 4; ++j) acc[mt][nt][j] = 0.f;

    load_stage(0); CP_COMMIT();
    load_stage(1); CP_COMMIT();

    for (int i = 0; i < KITERS; ++i) {
        CP_WAIT(1);
        __syncthreads();
        const uint32_t sbuf = sbase + (uint32_t)(i % STAGES) * STAGE_BYTES;
        const bool do_load = (i + 2 < KITERS);

        uint32_t afr[2][4][4], bfr[2][4][4];
        ld_frags(sbuf, 0, afr[0], bfr[0]);

        #pragma unroll
        for (int ks = 0; ks < 4; ++ks) {
            const int cur = ks & 1, nxt = cur ^ 1;
            if (ks < 3) ld_frags(sbuf, ks + 1, afr[nxt], bfr[nxt]);
            #pragma unroll
            for (int mt = 0; mt < 4; ++mt)
                #pragma unroll
                for (int p = 0; p < 4; ++p) {
                    mma16816(acc[mt][2 * p],     afr[cur][mt], &bfr[cur][p][0]);
                    mma16816(acc[mt][2 * p + 1], afr[cur][mt], &bfr[cur][p][2]);
                }
            if (do_load) load_quarter(i + 2, ks);
        }
        CP_COMMIT();
    }

    const int mbase = m0 + warp_m * 64 + (lid >> 2);
    const int nbase = n0 + warp_n * 64 + (lid & 3) * 2;
    #pragma unroll
    for (int mt = 0; mt < 4; ++mt) {
        const int m = mbase + mt * 16;
        #pragma unroll
        for (int nt = 0; nt < 8; ++nt) {
            const int n = nbase + nt * 8;
            const float2 bv = *reinterpret_cast<const float2*>(bias + n);
            float2 v0 = { acc[mt][nt][0] + bv.x, acc[mt][nt][1] + bv.y };
            float2 v1 = { acc[mt][nt][2] + bv.x, acc[mt][nt][3] + bv.y };
            *reinterpret_cast<float2*>(out + (size_t)m * N_TOTAL + n)       = v0;
            *reinterpret_cast<float2*>(out + (size_t)(m + 8) * N_TOTAL + n) = v1;
        }
    }
}

// ===================== launch: spin-gated conv overlap, side stream joined POST-GEMM =====
extern "C" void kernel_launch(void* const* d_in, const int* in_sizes, int n_in,
                              void* d_out, int out_size) {
    const float* x    = (const float*)d_in[0];
    const float* c0   = (const float*)d_in[1];
    const float* c1   = (const float*)d_in[2];
    const float* c2   = (const float*)d_in[3];
    const float* c3   = (const float*)d_in[4];
    const float* bias = (const float*)d_in[5];
    float* out = (float*)d_out;

    cudaFuncSetAttribute(k_gemm, cudaFuncAttributeMaxDynamicSharedMemorySize, SMEM_TOTAL);
    cudaFuncSetAttribute(k_buildW_mma, cudaFuncAttributeMaxDynamicSharedMemorySize, STAGE_BYTES);

    cudaStream_t s1;
    cudaStreamCreateWithFlags(&s1, cudaStreamNonBlocking);
    cudaEvent_t eFork, eJoin;
    cudaEventCreateWithFlags(&eFork, cudaEventDisableTiming);
    cudaEventCreateWithFlags(&eJoin, cudaEventDisableTiming);

    cudaEventRecord(eFork, 0);
    cudaStreamWaitEvent(s1, eFork, 0);

    // Branch A (side): x -> fp16. The GEMM node does NOT depend on this in the
    // graph; data readiness is enforced by the per-M-group spin gate.
    k_conv<<<16384, 256, 0, s1>>>(x);

    // Branch B (main): TT pairs -> W via HMMA.
    k_prep<<<2048, 256>>>(c0, c1, c2, c3);
    k_buildW_mma<<<1024, 128, STAGE_BYTES>>>();

    // GEMM launches immediately after W is ready (no wait on conv).
    k_gemm<<<(M_TOTAL / BM) * (N_TOTAL / BN), 128, SMEM_TOTAL>>>(bias, out);

    // Join the side stream AFTER the GEMM so capture sees all work rejoined.
    cudaEventRecord(eJoin, s1);
    cudaStreamWaitEvent(0, eJoin, 0);
}

// round 17
// speedup vs baseline: 1.0181x; 1.0181x over previous
#include <cuda_runtime.h>
#include <cuda_fp16.h>
#include <cstdint>

// ===================== device scratch (no allocs allowed) =====================
__device__ __half g_t12h[64 * 64 * 64];         // [m=(o12,i12)][r]   (A of W-GEMM)
__device__ __half g_t34h[64 * 64 * 64];         // [n=(o34,i34)][r]   (B of W-GEMM)
__device__ __half g_W[4096ull * 4096ull];       // [n][k] fp16 (main GEMM B)
__device__ __half g_X[16384ull * 4096ull];      // [m][k] fp16 (main GEMM A)

// ===================== helpers =====================
__device__ __forceinline__ uint32_t smem_u32(const void* p) {
    uint32_t a;
    asm("{ .reg .u64 t; cvta.to.shared.u64 t, %1; cvt.u32.u64 %0, t; }" : "=r"(a) : "l"(p));
    return a;
}
__device__ __forceinline__ void cp16(uint32_t s, const void* g) {
    asm volatile("cp.async.cg.shared.global [%0], [%1], 16;" :: "r"(s), "l"(g));
}
#define CP_COMMIT() asm volatile("cp.async.commit_group;" ::: "memory")
#define CP_WAIT(n)  asm volatile("cp.async.wait_group %0;" :: "n"(n) : "memory")

__device__ __forceinline__ void ldsm_x4(uint32_t& r0, uint32_t& r1, uint32_t& r2, uint32_t& r3,
                                        uint32_t addr) {
    asm volatile("ldmatrix.sync.aligned.m8n8.x4.shared.b16 {%0,%1,%2,%3}, [%4];"
                 : "=r"(r0), "=r"(r1), "=r"(r2), "=r"(r3) : "r"(addr));
}
__device__ __forceinline__ void mma16816(float* d, const uint32_t* a, const uint32_t* b) {
    asm volatile("mma.sync.aligned.m16n8k16.row.col.f32.f16.f16.f32 "
                 "{%0,%1,%2,%3}, {%4,%5,%6,%7}, {%8,%9}, {%0,%1,%2,%3};"
                 : "+f"(d[0]), "+f"(d[1]), "+f"(d[2]), "+f"(d[3])
                 : "r"(a[0]), "r"(a[1]), "r"(a[2]), "r"(a[3]), "r"(b[0]), "r"(b[1]));
}

// ===================== problem constants =====================
static constexpr int M_TOTAL = 16384, N_TOTAL = 4096, K_TOTAL = 4096;
static constexpr int BM = 128, BN = 128, BK = 64, STAGES = 3;
static constexpr int KITERS = K_TOTAL / BK;                  // 64
static constexpr uint32_t ROW_B = 144;                       // 128B data + 16B pad
static constexpr uint32_t STAGE_ROWS = BM + BN;              // 256 (A: 0..127, B: 128..255)
static constexpr uint32_t STAGE_BYTES = STAGE_ROWS * ROW_B;  // 36864
static constexpr uint32_t SMEM_TOTAL = STAGES * STAGE_BYTES; // 110592 -> 2 CTAs/SM

// ===================== kernel 0: t12h / t34h (fp16 TT pair contractions) =================
__global__ __launch_bounds__(256) void k_prep(const float* __restrict__ c0,
                                              const float* __restrict__ c1,
                                              const float* __restrict__ c2,
                                              const float* __restrict__ c3) {
    int bid = blockIdx.x;
    if (bid < 1024) {
        int idx = bid * 256 + threadIdx.x;            // (o12, i12, r3)
        int r3 = idx & 63, i12 = (idx >> 6) & 63, o12 = idx >> 12;
        int i1 = i12 >> 3, i2 = i12 & 7, o1 = o12 >> 3, o2 = o12 & 7;
        const float* g1 = c0 + (i1 * 8 + o1) * 64;              // [r2]
        const float* g2 = c1 + (i2 * 8 + o2) * 64 + r3;         // + r2*4096
        float acc = 0.f;
        #pragma unroll 8
        for (int r2 = 0; r2 < 64; ++r2) acc += g1[r2] * g2[r2 * 4096];
        g_t12h[(o12 * 64 + i12) * 64 + r3] = __float2half_rn(acc);   // A[m][r]
    } else {
        int idx = (bid - 1024) * 256 + threadIdx.x;   // (r3, o34, i34)
        int i34 = idx & 63, o34 = (idx >> 6) & 63, r3 = idx >> 12;
        int i3 = i34 >> 3, i4 = i34 & 7, o3 = o34 >> 3, o4 = o34 & 7;
        const float* g3 = c2 + ((r3 * 8 + i3) * 8 + o3) * 64;   // [r4]
        const float* g4 = c3 + (i4 * 8 + o4);                   // + r4*64
        float acc = 0.f;
        #pragma unroll 8
        for (int r4 = 0; r4 < 64; ++r4) acc += g3[r4] * g4[r4 * 64];
        g_t34h[(o34 * 64 + i34) * 64 + r3] = __float2half_rn(acc);   // B[n][r] (transposed)
    }
}

// ===================== kernel 1a: W via HMMA (M=4096, N=4096, K=64) + MPO scatter ========
// W[(o12,o34)][(i12,i34)] = sum_r t12[(o12,i12)][r] * t34[(o34,i34)][r]
__global__ void __launch_bounds__(128, 2) k_buildW_mma(void) {
    extern __shared__ char smem[];
    const uint32_t sbase = smem_u32(smem);
    const int tid = threadIdx.x, wid = tid >> 5, lid = tid & 31;

    const int m0 = (blockIdx.x >> 5) * BM;    // m = (o12, i12)
    const int n0 = (blockIdx.x & 31) * BN;    // n = (o34, i34)

    const int warp_m = wid >> 1;
    const int warp_n = wid & 1;

    const uint32_t a_lane_off =
        (uint32_t)(warp_m * 64 + (lid & 7) + ((lid >> 3) & 1) * 8) * ROW_B +
        (uint32_t)((lid >> 4) & 1) * 16u;
    const uint32_t b_lane_off =
        (uint32_t)(BM + warp_n * 64 + (((lid >> 3) >> 1) & 1) * 8 + (lid & 7)) * ROW_B +
        (uint32_t)((lid >> 3) & 1) * 16u;

    // Single stage: K_TOTAL == BK == 64 (64 halves = 128B per row = 8 x 16B chunks).
    #pragma unroll
    for (int it = 0; it < 16; ++it) {
        const int idx = it * 128 + tid;          // 0..2047
        const int row = idx >> 3, c = idx & 7;
        const uint32_t sa = sbase + (uint32_t)row * ROW_B + (uint32_t)c * 16u;
        const __half* g = (row < BM)
            ? (g_t12h + (size_t)(m0 + row) * 64 + c * 8)
            : (g_t34h + (size_t)(n0 + row - BM) * 64 + c * 8);
        cp16(sa, g);
    }
    CP_COMMIT();
    CP_WAIT(0);
    __syncthreads();

    float acc[4][8][4];
    #pragma unroll
    for (int mt = 0; mt < 4; ++mt)
        #pragma unroll
        for (int nt = 0; nt < 8; ++nt)
            #pragma unroll
            for (int j = 0; j < 4; ++j) acc[mt][nt][j] = 0.f;

    #pragma unroll
    for (int ks = 0; ks < 4; ++ks) {
        const uint32_t koff = (uint32_t)ks * 32u;
        uint32_t afr[4][4], bfr[4][4];
        #pragma unroll
        for (int mt = 0; mt < 4; ++mt)
            ldsm_x4(afr[mt][0], afr[mt][1], afr[mt][2], afr[mt][3],
                    sbase + a_lane_off + (uint32_t)mt * (16u * ROW_B) + koff);
        #pragma unroll
        for (int p = 0; p < 4; ++p)
            ldsm_x4(bfr[p][0], bfr[p][1], bfr[p][2], bfr[p][3],
                    sbase + b_lane_off + (uint32_t)p * (16u * ROW_B) + koff);
        #pragma unroll
        for (int mt = 0; mt < 4; ++mt)
            #pragma unroll
            for (int p = 0; p < 4; ++p) {
                mma16816(acc[mt][2 * p],     afr[mt], &bfr[p][0]);
                mma16816(acc[mt][2 * p + 1], afr[mt], &bfr[p][2]);
            }
    }

    // Scatter epilogue: (m=(o12,i12), n=(o34,i34)) -> g_W[(o12*64+o34)][(i12*64+i34)]
    const int mbase = m0 + warp_m * 64 + (lid >> 2);
    const int nbase = n0 + warp_n * 64 + (lid & 3) * 2;
    #pragma unroll
    for (int mt = 0; mt < 4; ++mt) {
        #pragma unroll
        for (int half = 0; half < 2; ++half) {          // rows m, m+8 of the fragment
            const int m = mbase + mt * 16 + half * 8;
            const int o12 = m >> 6, i12 = m & 63;
            #pragma unroll
            for (int nt = 0; nt < 8; ++nt) {
                const int n = nbase + nt * 8;           // i34 stays within its 64-block
                const int o34 = n >> 6, i34 = n & 63;
                const size_t addr = (size_t)(o12 * 64 + o34) * 4096 + i12 * 64 + i34;
                __half2 v = __floats2half2_rn(acc[mt][nt][2 * half],
                                              acc[mt][nt][2 * half + 1]);
                *reinterpret_cast<__half2*>(&g_W[addr]) = v;
            }
        }
    }
}

// ===================== kernel 1b: convert x -> fp16 (MLP=4) ==============================
__global__ __launch_bounds__(256) void k_conv(const float* __restrict__ x) {
    // 16384 blocks x 256 threads x 4 float4 = 16777216 float4 total.
    const size_t base = (size_t)blockIdx.x * 1024 + threadIdx.x;
    const float4* __restrict__ xi = reinterpret_cast<const float4*>(x);
    __half2* __restrict__ xo = reinterpret_cast<__half2*>(g_X);
    float4 v[4];
    #pragma unroll
    for (int j = 0; j < 4; ++j) v[j] = xi[base + j * 256];      // 4 independent loads in flight
    #pragma unroll
    for (int j = 0; j < 4; ++j) {
        const size_t t = base + j * 256;
        xo[2 * t]     = __floats2half2_rn(v[j].x, v[j].y);
        xo[2 * t + 1] = __floats2half2_rn(v[j].z, v[j].w);
    }
}

// ===================== kernel 2: GEMM 128x128x64, 4 warps of 64x64, 2 CTAs/SM ============
// FROZEN (R9/R10): interleaved cp.async + frag pipelining, tensor pipe 83%.
__global__ void __launch_bounds__(128, 2) k_gemm(const float* __restrict__ bias,
                                                 float* __restrict__ out) {
    extern __shared__ char smem[];
    const uint32_t sbase = smem_u32(smem);
    const int tid = threadIdx.x, wid = tid >> 5, lid = tid & 31;

    const int m0 = (blockIdx.x >> 5) * BM;
    const int n0 = (blockIdx.x & 31) * BN;

    const int warp_m = wid >> 1;
    const int warp_n = wid & 1;

    const uint32_t a_lane_off =
        (uint32_t)(warp_m * 64 + (lid & 7) + ((lid >> 3) & 1) * 8) * ROW_B +
        (uint32_t)((lid >> 4) & 1) * 16u;
    const uint32_t b_lane_off =
        (uint32_t)(BM + warp_n * 64 + (((lid >> 3) >> 1) & 1) * 8 + (lid & 7)) * ROW_B +
        (uint32_t)((lid >> 3) & 1) * 16u;

    const __half* __restrict__ Ag = g_X + (size_t)m0 * K_TOTAL;
    const __half* __restrict__ Bg = g_W + (size_t)n0 * K_TOTAL;

    auto load_quarter = [&](int st, int q) {
        const uint32_t sbuf = sbase + (uint32_t)(st % STAGES) * STAGE_BYTES;
        const int kk = st * BK;
        #pragma unroll
        for (int it = 0; it < 4; ++it) {
            const int idx = (q * 4 + it) * 128 + tid;
            const int row = idx >> 3, c = idx & 7;
            const uint32_t sa = sbuf + (uint32_t)row * ROW_B + (uint32_t)c * 16u;
            const __half* g = (row < BM)
                ? (Ag + (size_t)row * K_TOTAL + kk + c * 8)
                : (Bg + (size_t)(row - BM) * K_TOTAL + kk + c * 8);
            cp16(sa, g);
        }
    };
    auto load_stage = [&](int st) {
        #pragma unroll
        for (int q = 0; q < 4; ++q) load_quarter(st, q);
    };

    auto ld_frags = [&](uint32_t sbuf, int ks, uint32_t afr[4][4], uint32_t bfr[4][4]) {
        const uint32_t koff = (uint32_t)ks * 32u;
        #pragma unroll
        for (int mt = 0; mt < 4; ++mt)
            ldsm_x4(afr[mt][0], afr[mt][1], afr[mt][2], afr[mt][3],
                    sbuf + a_lane_off + (uint32_t)mt * (16u * ROW_B) + koff);
        #pragma unroll
        for (int p = 0; p < 4; ++p)
            ldsm_x4(bfr[p][0], bfr[p][1], bfr[p][2], bfr[p][3],
                    sbuf + b_lane_off + (uint32_t)p * (16u * ROW_B) + koff);
    };

    float acc[4][8][4];
    #pragma unroll
    for (int mt = 0; mt < 4; ++mt)
        #pragma unroll
        for (int nt = 0; nt < 8; ++nt)
            #pragma unroll
            for (int j = 0; j < 4; ++j) acc[mt][nt][j] = 0.f;

    load_stage(0); CP_COMMIT();
    load_stage(1); CP_COMMIT();

    for (int i = 0; i < KITERS; ++i) {
        CP_WAIT(1);
        __syncthreads();
        const uint32_t sbuf = sbase + (uint32_t)(i % STAGES) * STAGE_BYTES;
        const bool do_load = (i + 2 < KITERS);

        uint32_t afr[2][4][4], bfr[2][4][4];
        ld_frags(sbuf, 0, afr[0], bfr[0]);

        #pragma unroll
        for (int ks = 0; ks < 4; ++ks) {
            const int cur = ks & 1, nxt = cur ^ 1;
            if (ks < 3) ld_frags(sbuf, ks + 1, afr[nxt], bfr[nxt]);
            #pragma unroll
            for (int mt = 0; mt < 4; ++mt)
                #pragma unroll
                for (int p = 0; p < 4; ++p) {
                    mma16816(acc[mt][2 * p],     afr[cur][mt], &bfr[cur][p][0]);
                    mma16816(acc[mt][2 * p + 1], afr[cur][mt], &bfr[cur][p][2]);
                }
            if (do_load) load_quarter(i + 2, ks);
        }
        CP_COMMIT();
    }

    const int mbase = m0 + warp_m * 64 + (lid >> 2);
    const int nbase = n0 + warp_n * 64 + (lid & 3) * 2;
    #pragma unroll
    for (int mt = 0; mt < 4; ++mt) {
        const int m = mbase + mt * 16;
        #pragma unroll
        for (int nt = 0; nt < 8; ++nt) {
            const int n = nbase + nt * 8;
            const float2 bv = *reinterpret_cast<const float2*>(bias + n);
            float2 v0 = { acc[mt][nt][0] + bv.x, acc[mt][nt][1] + bv.y };
            float2 v1 = { acc[mt][nt][2] + bv.x, acc[mt][nt][3] + bv.y };
            *reinterpret_cast<float2*>(out + (size_t)m * N_TOTAL + n)       = v0;
            *reinterpret_cast<float2*>(out + (size_t)(m + 8) * N_TOTAL + n) = v1;
        }
    }
}

// ===================== launch: R13 fork/join + HIGH-PRIORITY conv stream ================
extern "C" void kernel_launch(void* const* d_in, const int* in_sizes, int n_in,
                              void* d_out, int out_size) {
    const float* x    = (const float*)d_in[0];
    const float* c0   = (const float*)d_in[1];
    const float* c1   = (const float*)d_in[2];
    const float* c2   = (const float*)d_in[3];
    const float* c3   = (const float*)d_in[4];
    const float* bias = (const float*)d_in[5];
    float* out = (float*)d_out;

    cudaFuncSetAttribute(k_gemm, cudaFuncAttributeMaxDynamicSharedMemorySize, SMEM_TOTAL);
    cudaFuncSetAttribute(k_buildW_mma, cudaFuncAttributeMaxDynamicSharedMemorySize, STAGE_BYTES);

    // Conv is the binding pre-GEMM branch: give its stream HIGH priority so the
    // HW scheduler places conv CTAs ahead of prep/buildW when they compete,
    // compressing conv toward its DRAM floor. Branch B (41us of work) still
    // finishes within conv's shadow.
    int prioLo, prioHi;
    cudaDeviceGetStreamPriorityRange(&prioLo, &prioHi);
    cudaStream_t s1;
    cudaStreamCreateWithPriority(&s1, cudaStreamNonBlocking, prioHi);
    cudaEvent_t eFork, eJoin;
    cudaEventCreateWithFlags(&eFork, cudaEventDisableTiming);
    cudaEventCreateWithFlags(&eJoin, cudaEventDisableTiming);

    cudaEventRecord(eFork, 0);
    cudaStreamWaitEvent(s1, eFork, 0);

    // Branch A (side, high prio): x -> fp16, whole tensor (never co-run with the GEMM).
    k_conv<<<16384, 256, 0, s1>>>(x);

    // Branch B (main): TT pairs -> W via HMMA.
    k_prep<<<2048, 256>>>(c0, c1, c2, c3);
    k_buildW_mma<<<1024, 128, STAGE_BYTES>>>();

    cudaEventRecord(eJoin, s1);
    cudaStreamWaitEvent(0, eJoin, 0);

    // Single GEMM launch — splitting it costs a ~40us drain (R12 post-mortem).
    k_gemm<<<(M_TOTAL / BM) * (N_TOTAL / BN), 128, SMEM_TOTAL>>>(bias, out);
}